// round 2
// baseline (speedup 1.0000x reference)
#include <cuda_runtime.h>

#define N_TOTAL 2097152
#define W 20
#define KSEL 62914            /* int(N * 0.03) */
#define CHUNK 4096
#define NT 256
#define NB (N_TOTAL / CHUNK)  /* 512 */
#define TPE (CHUNK / NT)      /* 16 */
#define NBINS 2048

#define SP(i) ((i) + ((i) >> 5))   /* shared padding: conflict-free strided access */

// ---------------- device globals (no allocation allowed) ----------------
__device__ float   g_r[N_TOTAL];
// 0:sum_r 1:sumsq_r 2:sumabs_r 3:sumabs_dr 4:sumabs_ds 5:sum_vol 6:sumsq_vol 7:pos 8:signprod
__device__ double  g_acc[9];
__device__ unsigned g_hist0[NBINS];
__device__ unsigned g_hist1c[NBINS];
__device__ double  g_hist1s[NBINS];
__device__ double  g_sumlow;
__device__ float4  g_chunkDD[NB];
__device__ int     g_b0;
__device__ long long g_below0;
__device__ double  g_dd;

// ---------------- helpers ----------------
__device__ __forceinline__ float bredF(float v, float* buf) {
    unsigned lane = threadIdx.x & 31u, w = threadIdx.x >> 5;
#pragma unroll
    for (int o = 16; o; o >>= 1) v += __shfl_down_sync(0xffffffffu, v, o);
    if (lane == 0) buf[w] = v;
    __syncthreads();
    float r = 0.f;
    if (threadIdx.x < 8) r = buf[threadIdx.x];
    if (w == 0) {
#pragma unroll
        for (int o = 4; o; o >>= 1) r += __shfl_down_sync(0xffu, r, o);
    }
    __syncthreads();
    return r;  // valid in thread 0
}

__device__ __forceinline__ double bredD(double v, double* buf) {
    unsigned lane = threadIdx.x & 31u, w = threadIdx.x >> 5;
#pragma unroll
    for (int o = 16; o; o >>= 1) v += __shfl_down_sync(0xffffffffu, v, o);
    if (lane == 0) buf[w] = v;
    __syncthreads();
    double r = 0.0;
    if (threadIdx.x < 8) r = buf[threadIdx.x];
    if (w == 0) {
#pragma unroll
        for (int o = 4; o; o >>= 1) r += __shfl_down_sync(0xffu, r, o);
    }
    __syncthreads();
    return r;
}

// Find k-th smallest bin in a 2048-bin histogram. 256 threads, 8 bins each.
__device__ void findKth(const unsigned* __restrict__ hist, long long target,
                        int* bin_out, long long* below_out) {
    __shared__ unsigned fkw[8];
    int t = threadIdx.x;
    unsigned lane = t & 31u, w = t >> 5;
    unsigned c[8], incl[8];
    unsigned run = 0;
#pragma unroll
    for (int j = 0; j < 8; j++) { c[j] = hist[t * 8 + j]; run += c[j]; incl[j] = run; }
    unsigned x = run;
#pragma unroll
    for (int o = 1; o < 32; o <<= 1) {
        unsigned yv = __shfl_up_sync(0xffffffffu, x, o);
        if (lane >= (unsigned)o) x += yv;
    }
    if (lane == 31) fkw[w] = x;
    __syncthreads();
    if (t == 0) {
        unsigned acc = 0;
        for (int i = 0; i < 8; i++) { unsigned tmp = fkw[i]; fkw[i] = acc; acc += tmp; }
    }
    __syncthreads();
    long long excl = (long long)fkw[w] + (long long)(x - run);
    if (excl < target && target <= excl + (long long)run) {
        bool found = false;
#pragma unroll
        for (int j = 0; j < 8; j++) {
            if (!found && excl + (long long)incl[j] >= target) {
                found = true;
                *bin_out = t * 8 + j;
                *below_out = excl + (long long)incl[j] - (long long)c[j];
            }
        }
    }
    __syncthreads();
}

struct DDS { double t, p, m, d; };
__device__ __forceinline__ DDS ddcomb(const DDS& a, const DDS& b) {
    DDS r;
    r.t = a.t + b.t;
    r.p = fmax(a.p, a.t + b.p);
    r.m = fmin(a.m, a.t + b.m);
    r.d = fmax(fmax(a.d, b.d), a.p - (a.t + b.m));
    return r;
}

// ---------------- kernels ----------------
__global__ void resetK() {
    int i = blockIdx.x * blockDim.x + threadIdx.x;
    if (i < NBINS) { g_hist0[i] = 0; g_hist1c[i] = 0; g_hist1s[i] = 0.0; }
    if (i < 9) g_acc[i] = 0.0;
    if (i == 9) g_sumlow = 0.0;
}

__global__ void __launch_bounds__(NT) pass1(const float* __restrict__ pred,
                                            const float* __restrict__ ret) {
    __shared__ float sh_r[SP(CHUNK + W - 1) + 1];
    __shared__ float sh_s[SP(CHUNK) + 1];
    __shared__ unsigned shist[NBINS];
    __shared__ float ddT[NT], ddP[NT], ddM[NT], ddD[NT];
    __shared__ float rbuf[8];

    int tid = threadIdx.x;
    int base = blockIdx.x * CHUNK;

    for (int b = tid; b < NBINS; b += NT) shist[b] = 0;
    __syncthreads();

    // Phase A: compute signals + r, store r, build level-0 histogram
    for (int idx = tid; idx < CHUNK + W; idx += NT) {
        int gi = base + idx;
        float s = 0.f, r = 0.f;
        if (gi < N_TOTAL) { s = tanhf(pred[gi]); r = ret[gi] * s; }
        sh_r[SP(idx)] = r;
        if (idx <= CHUNK) sh_s[SP(idx)] = s;
        if (idx < CHUNK) {
            g_r[gi] = r;
            unsigned u = __float_as_uint(r);
            unsigned key = (u & 0x80000000u) ? ~u : (u | 0x80000000u);
            unsigned bb = key >> 21;
            unsigned mask = __match_any_sync(0xffffffffu, bb);
            int leader = __ffs(mask) - 1;
            if ((int)(tid & 31) == leader) atomicAdd(&shist[bb], (unsigned)__popc(mask));
        }
    }
    __syncthreads();

    // Phase B: per-thread contiguous segment
    int start = tid * TPE;
    float sr = 0, sr2 = 0, sab = 0, sadr = 0, sads = 0, svol = 0, svol2 = 0;
    float fpos = 0, fsp = 0;
    float wsum = 0, wsum2 = 0;
#pragma unroll
    for (int j = 0; j < W; j++) { float v = sh_r[SP(start + j)]; wsum += v; wsum2 += v * v; }
    float cum = 0, peak = -3.4e38f, mn = 3.4e38f, ddv = 0;
#pragma unroll
    for (int j = 0; j < TPE; j++) {
        int li = start + j;
        int gi = base + li;
        float v = sh_r[SP(li)];
        sr += v; sr2 += v * v; sab += fabsf(v);
        fpos += (v > 0.f) ? 1.f : 0.f;
        cum += v;
        peak = fmaxf(peak, cum);
        mn = fminf(mn, cum);
        ddv = fmaxf(ddv, peak - cum);
        if (gi < N_TOTAL - 1) {
            float vn = sh_r[SP(li + 1)];
            sadr += fabsf(vn - v);
            float s0 = (v > 0.f) ? 1.f : ((v < 0.f) ? -1.f : 0.f);
            float s1 = (vn > 0.f) ? 1.f : ((vn < 0.f) ? -1.f : 0.f);
            fsp += s0 * s1;
            sads += fabsf(sh_s[SP(li + 1)] - sh_s[SP(li)]);
        }
        if (gi < N_TOTAL - W) {  // window k in [0, n-W)
            float varw = (wsum2 - wsum * wsum * (1.0f / W)) * (1.0f / (W - 1));
            varw = fmaxf(varw, 0.f);
            float vol = sqrtf(varw);
            svol += vol; svol2 += vol * vol;
        }
        float va = sh_r[SP(li + W)];
        wsum += va - v; wsum2 += va * va - v * v;
    }

    ddT[tid] = cum; ddP[tid] = peak; ddM[tid] = mn; ddD[tid] = ddv;

    // reductions (each call has internal barriers; ddT.. untouched by them)
    float t0 = bredF(sr, rbuf);
    float t1 = bredF(sr2, rbuf);
    float t2 = bredF(sab, rbuf);
    float t3 = bredF(sadr, rbuf);
    float t4 = bredF(sads, rbuf);
    float t5 = bredF(svol, rbuf);
    float t6 = bredF(svol2, rbuf);
    float t7 = bredF(fpos, rbuf);
    float t8 = bredF(fsp, rbuf);
    if (tid == 0) {
        atomicAdd(&g_acc[0], (double)t0);
        atomicAdd(&g_acc[1], (double)t1);
        atomicAdd(&g_acc[2], (double)t2);
        atomicAdd(&g_acc[3], (double)t3);
        atomicAdd(&g_acc[4], (double)t4);
        atomicAdd(&g_acc[5], (double)t5);
        atomicAdd(&g_acc[6], (double)t6);
        atomicAdd(&g_acc[7], (double)t7);
        atomicAdd(&g_acc[8], (double)t8);
    }

    // ordered tree combine of per-thread drawdown states
    __syncthreads();
    for (int s = 1; s < NT; s <<= 1) {
        if ((tid & (2 * s - 1)) == 0) {
            float at = ddT[tid], ap = ddP[tid], am = ddM[tid], ad = ddD[tid];
            float bt = ddT[tid + s], bp = ddP[tid + s], bm = ddM[tid + s], bd = ddD[tid + s];
            ddT[tid] = at + bt;
            ddP[tid] = fmaxf(ap, at + bp);
            ddM[tid] = fminf(am, at + bm);
            ddD[tid] = fmaxf(fmaxf(ad, bd), ap - (at + bm));
        }
        __syncthreads();
    }
    if (tid == 0)
        g_chunkDD[blockIdx.x] = make_float4(ddT[0], ddP[0], ddM[0], ddD[0]);

    // merge level-0 histogram
    for (int b = tid; b < NBINS; b += NT) {
        unsigned c = shist[b];
        if (c) atomicAdd(&g_hist0[b], c);
    }
}

__global__ void __launch_bounds__(NT) kernelA() {
    __shared__ double sT[NT], sP[NT], sM[NT], sD[NT];
    int t = threadIdx.x;
    float4 x = g_chunkDD[2 * t];
    float4 y = g_chunkDD[2 * t + 1];
    DDS A = { (double)x.x, (double)x.y, (double)x.z, (double)x.w };
    DDS B = { (double)y.x, (double)y.y, (double)y.z, (double)y.w };
    DDS c = ddcomb(A, B);
    sT[t] = c.t; sP[t] = c.p; sM[t] = c.m; sD[t] = c.d;
    __syncthreads();
    for (int s = 1; s < NT; s <<= 1) {
        if ((t & (2 * s - 1)) == 0) {
            DDS a = { sT[t], sP[t], sM[t], sD[t] };
            DDS b = { sT[t + s], sP[t + s], sM[t + s], sD[t + s] };
            DDS r = ddcomb(a, b);
            sT[t] = r.t; sP[t] = r.p; sM[t] = r.m; sD[t] = r.d;
        }
        __syncthreads();
    }
    if (t == 0) g_dd = sD[0];

    findKth(g_hist0, (long long)KSEL, &g_b0, &g_below0);
}

__global__ void __launch_bounds__(NT) pass2() {
    __shared__ unsigned hc[NBINS];
    __shared__ float hs[NBINS];
    __shared__ float rbuf[8];
    int tid = threadIdx.x;
    for (int b = tid; b < NBINS; b += NT) { hc[b] = 0; hs[b] = 0.f; }
    __syncthreads();
    int b0 = g_b0;
    float lsum = 0.f;
    int stride = gridDim.x * blockDim.x;
    for (int i = blockIdx.x * blockDim.x + tid; i < N_TOTAL; i += stride) {
        float v = g_r[i];
        unsigned u = __float_as_uint(v);
        unsigned key = (u & 0x80000000u) ? ~u : (u | 0x80000000u);
        int h = (int)(key >> 21);
        if (h < b0) {
            lsum += v;
        } else if (h == b0) {
            unsigned sb = (key >> 10) & 2047u;
            atomicAdd(&hc[sb], 1u);
            atomicAdd(&hs[sb], v);
        }
    }
    float ts = bredF(lsum, rbuf);
    if (tid == 0) atomicAdd(&g_sumlow, (double)ts);
    __syncthreads();
    for (int b = tid; b < NBINS; b += NT) {
        if (hc[b]) {
            atomicAdd(&g_hist1c[b], hc[b]);
            atomicAdd(&g_hist1s[b], (double)hs[b]);
        }
    }
}

__global__ void __launch_bounds__(NT) kernelB(float* __restrict__ out) {
    __shared__ int sb1;
    __shared__ long long sbelow1;
    __shared__ double dbuf[8];
    int tid = threadIdx.x;
    long long below0 = g_below0;
    long long target2 = (long long)KSEL - below0;
    findKth(g_hist1c, target2, &sb1, &sbelow1);
    __syncthreads();
    int b1 = sb1;
    long long below1 = sbelow1;
    double part = 0.0;
    for (int b = tid; b < NBINS; b += NT)
        if (b < b1) part += g_hist1s[b];
    double mid = bredD(part, dbuf);
    if (tid == 0) {
        long long m = target2 - below1;
        unsigned keylo = ((unsigned)g_b0 << 21) | ((unsigned)b1 << 10);
        unsigned ub = (keylo & 0x80000000u) ? (keylo ^ 0x80000000u) : ~keylo;
        float vlo = __uint_as_float(ub);
        double tail = g_sumlow + mid + (double)m * (double)vlo;
        double cvar = -tail / (double)KSEL;

        double n = (double)N_TOTAL;
        double sum_r = g_acc[0], sumsq = g_acc[1], sabs = g_acc[2];
        double sadr = g_acc[3], sads = g_acc[4], svol = g_acc[5], svol2 = g_acc[6];
        double posc = g_acc[7], spc = g_acc[8];

        double mean = sum_r / n;
        double stdr = sqrt(fmax((sumsq - sum_r * sum_r / n) / (n - 1.0), 0.0)) + 1e-8;
        double base_sharpe = mean / stdr;
        double nw = n - (double)W;
        double stdv = sqrt(fmax((svol2 - svol * svol / nw) / (nw - 1.0), 0.0));
        double vol_stab = 1.0 / (stdv + 1e-6);
        double enhanced = base_sharpe * (1.0 + 0.1 * vol_stab);
        double rm = sabs / n;
        double pf = posc / n;
        double madr = sadr / (n - 1.0);
        double rs = 1.0 / (madr + 1e-6);
        double mc = spc / (n - 1.0);
        double ddpen = fmax(g_dd - 0.05, 0.0);
        double scm = sads / (n - 1.0);
        double ss = 1.0 / (scm + 1e-6);
        double shc = 0.4 * enhanced + 0.25 * rm + 0.15 * pf + 0.1 * mc + 0.05 * rs + 0.05 * ss;
        double risk = 0.05 * cvar + 0.02 * ddpen + 0.01 * scm;
        double loss = -(0.6 * rm + 0.4 * shc - risk);
        out[0] = (float)loss;
    }
}

// ---------------- launch ----------------
extern "C" void kernel_launch(void* const* d_in, const int* in_sizes, int n_in,
                              void* d_out, int out_size) {
    (void)in_sizes; (void)n_in; (void)out_size;
    const float* pred = (const float*)d_in[0];
    const float* ret  = (const float*)d_in[1];
    float* out = (float*)d_out;

    resetK<<<8, NT>>>();
    pass1<<<NB, NT>>>(pred, ret);
    kernelA<<<1, NT>>>();
    pass2<<<NB, NT>>>();
    kernelB<<<1, NT>>>(out);
}

// round 4
// speedup vs baseline: 1.5991x; 1.5991x over previous
#include <cuda_runtime.h>

#define N_TOTAL 2097152
#define W 20
#define KSEL 62914            /* int(N * 0.03) */
#define CHUNK 4096
#define NT 256
#define NB (N_TOTAL / CHUNK)  /* 512 */
#define TPE (CHUNK / NT)      /* 16 */
#define HB 2048               /* histogram bins (negatives only), 6 mantissa bits */

#define SP(i) ((i) + ((i) >> 5))   /* shared padding: conflict-free strided access */

// ---------------- device globals (zero-init; finalize kernel re-zeros) ----
// 0:sum_r 1:sumsq_r 2:sumabs_r 3:sumabs_dr 4:sumabs_ds 5:sum_vol 6:sumsq_vol 7:pos 8:signprod
__device__ double   g_acc[9];
__device__ unsigned g_histc[HB];
__device__ double   g_hists[HB];
__device__ float4   g_chunkDD[NB];

// ---------------- helpers ----------------
__device__ __forceinline__ double bredD(double v, double* buf) {
    unsigned lane = threadIdx.x & 31u, w = threadIdx.x >> 5;
#pragma unroll
    for (int o = 16; o; o >>= 1) v += __shfl_down_sync(0xffffffffu, v, o);
    if (lane == 0) buf[w] = v;
    __syncthreads();
    double r = 0.0;
    if (threadIdx.x < 8) r = buf[threadIdx.x];
    if (w == 0) {
#pragma unroll
        for (int o = 4; o; o >>= 1) r += __shfl_down_sync(0xffu, r, o);
    }
    __syncthreads();
    return r;  // valid in thread 0
}

// negatives-only magnitude histogram: more negative -> smaller idx
__device__ __forceinline__ void histAdd(float v, unsigned* shc, float* shs) {
    if (v < 0.f) {
        unsigned u = __float_as_uint(v);
        int E = (int)((u >> 23) & 255u);
        int idx;
        if (E > 130) idx = 0;
        else {
            int mant = (int)((u >> 17) & 63u);
            idx = (130 - E) * 64 + (63 - mant);
            if (idx > HB - 1) idx = HB - 1;
        }
        atomicAdd(&shc[idx], 1u);
        atomicAdd(&shs[idx], v);
    }
}

// ---------------- pass1: single data pass ----------------
__global__ void __launch_bounds__(NT) pass1(const float* __restrict__ pred,
                                            const float* __restrict__ ret) {
    __shared__ float sh_r[SP(CHUNK + W) + 1];
    __shared__ float sh_s[SP(CHUNK + W) + 1];
    __shared__ unsigned shc[HB];
    __shared__ float shs[HB];
    __shared__ float sred[8 * 9];
    __shared__ float sddT[8], sddP[8], sddM[8], sddD[8];

    const int tid = threadIdx.x;
    const int base = blockIdx.x * CHUNK;
    const unsigned lane = tid & 31u, wrp = tid >> 5;

    for (int b = tid; b < HB; b += NT) { shc[b] = 0; shs[b] = 0.f; }
    __syncthreads();

    // ---- Phase A: vectorized compute of s = tanh(pred), r = ret*s ----
    const float4* p4 = reinterpret_cast<const float4*>(pred + base);
    const float4* q4 = reinterpret_cast<const float4*>(ret + base);
#pragma unroll
    for (int it = 0; it < CHUNK / 4 / NT; it++) {
        int vi = tid + it * NT;
        float4 p = p4[vi];
        float4 q = q4[vi];
        float s0 = tanhf(p.x), s1 = tanhf(p.y), s2 = tanhf(p.z), s3 = tanhf(p.w);
        float r0 = q.x * s0, r1 = q.y * s1, r2 = q.z * s2, r3 = q.w * s3;
        int li = vi * 4;
        sh_s[SP(li + 0)] = s0; sh_s[SP(li + 1)] = s1;
        sh_s[SP(li + 2)] = s2; sh_s[SP(li + 3)] = s3;
        sh_r[SP(li + 0)] = r0; sh_r[SP(li + 1)] = r1;
        sh_r[SP(li + 2)] = r2; sh_r[SP(li + 3)] = r3;
        histAdd(r0, shc, shs); histAdd(r1, shc, shs);
        histAdd(r2, shc, shs); histAdd(r3, shc, shs);
    }
    // tail: next W elements (for windows / diffs crossing the chunk boundary)
    if (tid < W) {
        int gi = base + CHUNK + tid;
        float s = 0.f, r = 0.f;
        if (gi < N_TOTAL) { s = tanhf(pred[gi]); r = ret[gi] * s; }
        sh_s[SP(CHUNK + tid)] = s;
        sh_r[SP(CHUNK + tid)] = r;
    }
    __syncthreads();

    // ---- Phase B: per-thread contiguous segment ----
    const int start = tid * TPE;
    float sr = 0, sr2 = 0, sab = 0, sadr = 0, sads = 0, svol = 0, svol2 = 0;
    float fpos = 0, fsp = 0;
    float wsum = 0, wsum2 = 0;
#pragma unroll
    for (int j = 0; j < W; j++) { float v = sh_r[SP(start + j)]; wsum += v; wsum2 += v * v; }
    float cum = 0, peak = -3.4e38f, mn = 3.4e38f, ddv = 0;
#pragma unroll
    for (int j = 0; j < TPE; j++) {
        int li = start + j;
        int gi = base + li;
        float v = sh_r[SP(li)];
        sr += v; sr2 += v * v; sab += fabsf(v);
        fpos += (v > 0.f) ? 1.f : 0.f;
        cum += v;
        peak = fmaxf(peak, cum);
        mn = fminf(mn, cum);
        ddv = fmaxf(ddv, peak - cum);
        if (gi < N_TOTAL - 1) {
            float vn = sh_r[SP(li + 1)];
            sadr += fabsf(vn - v);
            float s0 = (v > 0.f) ? 1.f : ((v < 0.f) ? -1.f : 0.f);
            float s1 = (vn > 0.f) ? 1.f : ((vn < 0.f) ? -1.f : 0.f);
            fsp += s0 * s1;
            sads += fabsf(sh_s[SP(li + 1)] - sh_s[SP(li)]);
        }
        if (gi < N_TOTAL - W) {
            float varw = (wsum2 - wsum * wsum * (1.0f / W)) * (1.0f / (W - 1));
            varw = fmaxf(varw, 0.f);
            float vol = sqrtf(varw);
            svol += vol; svol2 += vol * vol;
        }
        float va = sh_r[SP(li + W)];
        wsum += va - v; wsum2 += va * va - v * v;
    }

    // ---- merged 9-way block reduction (commutative adds: butterfly ok) ----
    {
        float vals[9] = { sr, sr2, sab, sadr, sads, svol, svol2, fpos, fsp };
#pragma unroll
        for (int j = 0; j < 9; j++) {
#pragma unroll
            for (int o = 16; o; o >>= 1) vals[j] += __shfl_down_sync(0xffffffffu, vals[j], o);
        }
        if (lane == 0) {
#pragma unroll
            for (int j = 0; j < 9; j++) sred[wrp * 9 + j] = vals[j];
        }
    }

    // ---- drawdown: ORDERED Hillis-Steele inclusive scan (non-commutative!) ----
    // After the scan, lane i holds combine(state_0 .. state_i) in sequence order;
    // lane 31 holds the whole warp's ordered combine.
    {
        float t = cum, p = peak, m = mn, d = ddv;
#pragma unroll
        for (int o = 1; o < 32; o <<= 1) {
            float at = __shfl_up_sync(0xffffffffu, t, o);
            float ap = __shfl_up_sync(0xffffffffu, p, o);
            float am = __shfl_up_sync(0xffffffffu, m, o);
            float ad = __shfl_up_sync(0xffffffffu, d, o);
            if (lane >= (unsigned)o) {
                // combine a (predecessor segment) then b (self): uses OLD p/m/t of self
                d = fmaxf(fmaxf(ad, d), ap - (at + m));
                p = fmaxf(ap, at + p);
                m = fminf(am, at + m);
                t = at + t;
            }
        }
        if (lane == 31) { sddT[wrp] = t; sddP[wrp] = p; sddM[wrp] = m; sddD[wrp] = d; }
    }
    __syncthreads();

    if (tid < 9) {
        float a = 0.f;
#pragma unroll
        for (int w2 = 0; w2 < 8; w2++) a += sred[w2 * 9 + tid];
        atomicAdd(&g_acc[tid], (double)a);
    }
    if (wrp == 0 && lane < 8) {
        // ordered scan over the 8 per-warp states (lanes 0..7)
        float t = sddT[lane], p = sddP[lane], m = sddM[lane], d = sddD[lane];
#pragma unroll
        for (int o = 1; o < 8; o <<= 1) {
            float at = __shfl_up_sync(0xffu, t, o);
            float ap = __shfl_up_sync(0xffu, p, o);
            float am = __shfl_up_sync(0xffu, m, o);
            float ad = __shfl_up_sync(0xffu, d, o);
            if (lane >= (unsigned)o) {
                d = fmaxf(fmaxf(ad, d), ap - (at + m));
                p = fmaxf(ap, at + p);
                m = fminf(am, at + m);
                t = at + t;
            }
        }
        if (lane == 7) g_chunkDD[blockIdx.x] = make_float4(t, p, m, d);
    }

    // ---- flush histogram ----
    for (int b = tid; b < HB; b += NT) {
        unsigned c = shc[b];
        if (c) {
            atomicAdd(&g_histc[b], c);
            atomicAdd(&g_hists[b], (double)shs[b]);
        }
    }
}

// ---------------- finalize: dd combine, k-select, formula, reset ----------
struct DDS { double t, p, m, d; };
__device__ __forceinline__ DDS ddcomb(const DDS& a, const DDS& b) {
    DDS r;
    r.t = a.t + b.t;
    r.p = fmax(a.p, a.t + b.p);
    r.m = fmin(a.m, a.t + b.m);
    r.d = fmax(fmax(a.d, b.d), a.p - (a.t + b.m));
    return r;
}

__global__ void __launch_bounds__(NT) finalize(float* __restrict__ out) {
    __shared__ double sT[NT], sP[NT], sM[NT], sD[NT];
    __shared__ unsigned fkw[8];
    __shared__ int sb0;
    __shared__ long long sbelow;
    __shared__ double dbuf[8];
    const int t = threadIdx.x;
    const unsigned lane = t & 31u, wrp = t >> 5;

    // 1. drawdown combine over 512 chunk states — ORDERED shared tree
    {
        float4 x = g_chunkDD[2 * t];
        float4 y = g_chunkDD[2 * t + 1];
        DDS A = { (double)x.x, (double)x.y, (double)x.z, (double)x.w };
        DDS B = { (double)y.x, (double)y.y, (double)y.z, (double)y.w };
        DDS c = ddcomb(A, B);
        sT[t] = c.t; sP[t] = c.p; sM[t] = c.m; sD[t] = c.d;
    }
    __syncthreads();
    for (int s = 1; s < NT; s <<= 1) {
        if ((t & (2 * s - 1)) == 0) {
            DDS a = { sT[t], sP[t], sM[t], sD[t] };
            DDS b = { sT[t + s], sP[t + s], sM[t + s], sD[t + s] };
            DDS r = ddcomb(a, b);
            sT[t] = r.t; sP[t] = r.p; sM[t] = r.m; sD[t] = r.d;
        }
        __syncthreads();
    }
    double dd = sD[0];

    // 2. find k-th smallest bin (256 threads x 8 bins)
    {
        unsigned c[8], incl[8];
        unsigned run = 0;
#pragma unroll
        for (int j = 0; j < 8; j++) { c[j] = g_histc[t * 8 + j]; run += c[j]; incl[j] = run; }
        unsigned x = run;
#pragma unroll
        for (int o = 1; o < 32; o <<= 1) {
            unsigned yv = __shfl_up_sync(0xffffffffu, x, o);
            if (lane >= (unsigned)o) x += yv;
        }
        if (lane == 31) fkw[wrp] = x;
        __syncthreads();
        if (t == 0) {
            unsigned acc = 0;
            for (int i = 0; i < 8; i++) { unsigned tmp = fkw[i]; fkw[i] = acc; acc += tmp; }
        }
        __syncthreads();
        long long excl = (long long)fkw[wrp] + (long long)(x - run);
        long long target = (long long)KSEL;
        if (excl < target && target <= excl + (long long)run) {
            bool found = false;
#pragma unroll
            for (int j = 0; j < 8; j++) {
                if (!found && excl + (long long)incl[j] >= target) {
                    found = true;
                    sb0 = t * 8 + j;
                    sbelow = excl + (long long)incl[j] - (long long)c[j];
                }
            }
        }
        __syncthreads();
    }
    const int b0 = sb0;
    const long long below = sbelow;

    // 3. sum of bins strictly below b0
    double part = 0.0;
    for (int b = t; b < b0; b += NT) part += g_hists[b];
    double mid = bredD(part, dbuf);

    // 4. thread 0 snapshots everything it needs
    double Sb = 0.0; unsigned cb = 1;
    double acc[9];
    if (t == 0) {
        Sb = g_hists[b0];
        cb = g_histc[b0];
#pragma unroll
        for (int j = 0; j < 9; j++) acc[j] = g_acc[j];
    }
    __syncthreads();

    // 5. reset globals for next replay
    for (int b = t; b < HB; b += NT) { g_histc[b] = 0; g_hists[b] = 0.0; }
    if (t < 9) g_acc[t] = 0.0;

    // 6. final formula
    if (t == 0) {
        long long m = (long long)KSEL - below;
        double tail = mid + (double)m * (Sb / (double)cb);
        double cvar = -tail / (double)KSEL;

        double n = (double)N_TOTAL;
        double sum_r = acc[0], sumsq = acc[1], sabs = acc[2];
        double sadr = acc[3], sads = acc[4], svol = acc[5], svol2 = acc[6];
        double posc = acc[7], spc = acc[8];

        double mean = sum_r / n;
        double stdr = sqrt(fmax((sumsq - sum_r * sum_r / n) / (n - 1.0), 0.0)) + 1e-8;
        double base_sharpe = mean / stdr;
        double nw = n - (double)W;
        double stdv = sqrt(fmax((svol2 - svol * svol / nw) / (nw - 1.0), 0.0));
        double vol_stab = 1.0 / (stdv + 1e-6);
        double enhanced = base_sharpe * (1.0 + 0.1 * vol_stab);
        double rm = sabs / n;
        double pf = posc / n;
        double madr = sadr / (n - 1.0);
        double rs = 1.0 / (madr + 1e-6);
        double mc = spc / (n - 1.0);
        double ddpen = fmax(dd - 0.05, 0.0);
        double scm = sads / (n - 1.0);
        double ss = 1.0 / (scm + 1e-6);
        double shc2 = 0.4 * enhanced + 0.25 * rm + 0.15 * pf + 0.1 * mc + 0.05 * rs + 0.05 * ss;
        double risk = 0.05 * cvar + 0.02 * ddpen + 0.01 * scm;
        double loss = -(0.6 * rm + 0.4 * shc2 - risk);
        out[0] = (float)loss;
    }
}

// ---------------- launch ----------------
extern "C" void kernel_launch(void* const* d_in, const int* in_sizes, int n_in,
                              void* d_out, int out_size) {
    (void)in_sizes; (void)n_in; (void)out_size;
    const float* pred = (const float*)d_in[0];
    const float* ret  = (const float*)d_in[1];
    float* out = (float*)d_out;

    pass1<<<NB, NT>>>(pred, ret);
    finalize<<<1, NT>>>(out);
}